// round 16
// baseline (speedup 1.0000x reference)
#include <cuda_runtime.h>
#include <cuda_fp16.h>
#include <math.h>
#include <stdint.h>

#define BATCH  64
#define HD     128
#define OUTC   10

#define PITCHV 136      // V row pitch, fp16 elems
#define V0_OFF 0
#define V1_OFF (16 * PITCHV * 2)            // 4352
#define XS_OFF (2 * 16 * PITCHV * 2)        // 8704
#define LG_OFF (XS_OFF + 16 * 256 * 4)      // 25088
#define RI_OFF (LG_OFF + 64)
#define LT_OFF (RI_OFF + 64)
#define SMEM_MAIN (LT_OFF + 64)

// exact correction: 127 pair-steps x ln(64) + 1 single step x ln(8) = 255*ln(8)
#define LOG_CORR 530.25759f

// Pair products in B-fragment order (fp16 pairs in u32; 16.6 MB):
//   pair p covers sites 2p+1, 2p+2 (cores[2p], cores[2p+1])
//   P[k][n], n = 4h + c, c = aidx + 2*bidx combo
//   u32 idx: ((((p*8+wc)*8+nt)*4+kp)*32 + lane)*4 + j
//     kc = 2kp+(j>>1); k0 = kc*16+2*(lane&3)+((j&1)<<3); n = wc*64+nt*8+(lane>>2)
__device__ uint32_t g_pairperm[(size_t)127 * 32768];
// row-major temp for pair products: [p][c][k][h], fp16
__device__ __half g_pairtmp[(size_t)127 * 4 * 16384];
// site 254 (cores[254]) in single-site fragment layout (n = 2h+d)
__device__ uint32_t g_permlast[16384];

// ---------------- helpers ----------------
__device__ __forceinline__ uint32_t smem_u32(const void* p) {
    uint32_t a;
    asm("{ .reg .u64 t; cvta.to.shared.u64 t, %1; cvt.u32.u64 %0, t; }" : "=r"(a) : "l"(p));
    return a;
}
__device__ __forceinline__ void ldm_x4(uint32_t* r, uint32_t addr) {
    asm volatile("ldmatrix.sync.aligned.m8n8.x4.shared.b16 {%0,%1,%2,%3}, [%4];"
                 : "=r"(r[0]), "=r"(r[1]), "=r"(r[2]), "=r"(r[3]) : "r"(addr));
}
__device__ __forceinline__ void ldm_x4_t(uint32_t* r, uint32_t addr) {
    asm volatile("ldmatrix.sync.aligned.m8n8.x4.trans.shared.b16 {%0,%1,%2,%3}, [%4];"
                 : "=r"(r[0]), "=r"(r[1]), "=r"(r[2]), "=r"(r[3]) : "r"(addr));
}
// f16-accumulate HMMA (chain)
__device__ __forceinline__ void mma16816h(uint32_t* c, const uint32_t* a,
                                          uint32_t b0, uint32_t b1) {
    asm volatile(
        "mma.sync.aligned.m16n8k16.row.col.f16.f16.f16.f16 "
        "{%0,%1}, {%2,%3,%4,%5}, {%6,%7}, {%0,%1};"
        : "+r"(c[0]), "+r"(c[1])
        : "r"(a[0]), "r"(a[1]), "r"(a[2]), "r"(a[3]), "r"(b0), "r"(b1));
}
// f32-accumulate HMMA (pair-product precompute)
__device__ __forceinline__ void mma16816f(float* c, const uint32_t* a,
                                          uint32_t b0, uint32_t b1) {
    asm volatile(
        "mma.sync.aligned.m16n8k16.row.col.f32.f16.f16.f32 "
        "{%0,%1,%2,%3}, {%4,%5,%6,%7}, {%8,%9}, {%0,%1,%2,%3};"
        : "+f"(c[0]), "+f"(c[1]), "+f"(c[2]), "+f"(c[3])
        : "r"(a[0]), "r"(a[1]), "r"(a[2]), "r"(a[3]), "r"(b0), "r"(b1));
}
__device__ __forceinline__ uint32_t packh2(float a, float b) {
    __half2 t = __floats2half2_rn(a, b);
    return *reinterpret_cast<uint32_t*>(&t);
}

// ---------------- pair products: P_c = A_a @ B_b (128x128, f16 out) --------
__global__ void __launch_bounds__(256) pp_kernel(const float* __restrict__ cores)
{
    extern __shared__ __half psm[];
    __half (*As)[136] = (__half (*)[136])psm;
    __half (*Bs)[136] = (__half (*)[136])(psm + 128 * 136);
    const int c = blockIdx.x, p = blockIdx.y;
    const int aidx = c & 1, bidx = c >> 1;
    const int tid = threadIdx.x, lane = tid & 31, wid = tid >> 5;
    const int wr = wid >> 2, wcol = wid & 3;
    const float* pa = cores + (size_t)(2 * p) * 32768;
    const float* pb = pa + 32768;

    #pragma unroll 4
    for (int it = 0; it < 64; ++it) {
        int idx = it * 256 + tid;
        int k = idx >> 7, j = idx & 127;
        float a0 = pa[(size_t)k * 256 + j], a1 = pa[(size_t)k * 256 + 128 + j];
        As[k][j] = __float2half_rn(aidx ? (a1 - a0) : a0);
        float b0 = pb[(size_t)k * 256 + j], b1 = pb[(size_t)k * 256 + 128 + j];
        Bs[k][j] = __float2half_rn(bidx ? (b1 - b0) : b0);
    }
    __syncthreads();

    const int l15 = lane & 15, lhi = (lane >> 4) << 3;
    float acc[4][4][4];
    #pragma unroll
    for (int i = 0; i < 4; ++i)
        #pragma unroll
        for (int j = 0; j < 4; ++j)
            #pragma unroll
            for (int v = 0; v < 4; ++v) acc[i][j][v] = 0.f;

    #pragma unroll
    for (int kc = 0; kc < 8; ++kc) {
        uint32_t a[4][4], bf[2][4];
        #pragma unroll
        for (int mi = 0; mi < 4; ++mi)
            ldm_x4(a[mi], smem_u32(&As[wr * 64 + mi * 16 + l15][kc * 16 + lhi]));
        #pragma unroll
        for (int nb = 0; nb < 2; ++nb)
            ldm_x4_t(bf[nb], smem_u32(&Bs[kc * 16 + l15][wcol * 32 + nb * 16 + lhi]));
        #pragma unroll
        for (int mi = 0; mi < 4; ++mi)
            #pragma unroll
            for (int nj = 0; nj < 4; ++nj)
                mma16816f(acc[mi][nj], a[mi],
                          bf[nj >> 1][(nj & 1) * 2], bf[nj >> 1][(nj & 1) * 2 + 1]);
    }

    char* outp = (char*)(g_pairtmp + (((size_t)p * 4 + c) << 14));
    const int g = lane >> 2, q = lane & 3;
    #pragma unroll
    for (int mi = 0; mi < 4; ++mi) {
        int r0 = wr * 64 + mi * 16 + g;
        #pragma unroll
        for (int nj = 0; nj < 4; ++nj) {
            int col = wcol * 32 + nj * 8 + q * 2;
            *(uint32_t*)(outp + (size_t)r0 * 256 + col * 2) = packh2(acc[mi][nj][0], acc[mi][nj][1]);
            *(uint32_t*)(outp + (size_t)(r0 + 8) * 256 + col * 2) = packh2(acc[mi][nj][2], acc[mi][nj][3]);
        }
    }
}

// ---------------- permute pair products into fragment order ----------------
__global__ void __launch_bounds__(256) perm_pairs()
{
    size_t gid = (size_t)blockIdx.x * 256 + threadIdx.x;   // 127*32768
    int u = (int)(gid & 32767);
    int p = (int)(gid >> 15);
    int j    = u & 3;
    int lane = (u >> 2) & 31;
    int kp   = (u >> 7) & 3;
    int nt   = (u >> 9) & 7;
    int wc   = (u >> 12) & 7;
    int kc = 2 * kp + (j >> 1);
    int k0 = kc * 16 + 2 * (lane & 3) + ((j & 1) << 3);
    int n  = wc * 64 + nt * 8 + (lane >> 2);
    int c = n & 3, h = n >> 2;
    const unsigned short* base =
        (const unsigned short*)(g_pairtmp + (((size_t)p * 4 + c) << 14));
    uint32_t lo = base[(size_t)k0 * 128 + h];
    uint32_t hi = base[(size_t)(k0 + 1) * 128 + h];
    g_pairperm[gid] = lo | (hi << 16);
}

// ---------------- last site (cores[254]) single-site fragment permute -------
__global__ void __launch_bounds__(256) conv_last(const float* __restrict__ cores)
{
    int u = blockIdx.x * 256 + threadIdx.x;   // 16384
    int j    = u & 3;
    int lane = (u >> 2) & 31;
    int kp   = (u >> 7) & 3;
    int c8   = (u >> 9) & 31;
    int kc = 2 * kp + (j >> 1);
    int k0 = kc * 16 + 2 * (lane & 3) + ((j & 1) << 3);
    int n  = c8 * 8 + (lane >> 2);
    int h = n >> 1, d = n & 1;
    const float* base = cores + (size_t)254 * 32768;
    float lo = base[(size_t)k0 * 256 + d * 128 + h];
    float hi = base[(size_t)(k0 + 1) * 256 + d * 128 + h];
    g_permlast[u] = packh2(lo, hi);
}

// ---------------- renorm (256 threads, full 16x128 fp16 buffer) -------------
__device__ __forceinline__ void renorm(char* vb, float* LOGS, float* RINV)
{
    const int tid = threadIdx.x;
    __syncthreads();
    int bb = tid >> 4, seg = tid & 15;
    __half* vr = (__half*)(vb + bb * (PITCHV * 2));
    float s = 0.f;
    #pragma unroll
    for (int j = 0; j < 8; ++j) {
        float f = __half2float(vr[seg * 8 + j]);
        s = fmaf(f, f, s);
    }
    #pragma unroll
    for (int o = 8; o > 0; o >>= 1) s += __shfl_xor_sync(0xffffffffu, s, o);
    if (seg == 0) {
        float nrm = fmaxf(sqrtf(s), 1e-30f);
        LOGS[bb] += logf(nrm);
        RINV[bb] = 1.f / nrm;
    }
    __syncthreads();
    float ri = RINV[bb];
    #pragma unroll
    for (int j = 0; j < 8; ++j)
        vr[seg * 8 + j] = __float2half_rn(__half2float(vr[seg * 8 + j]) * ri);
}

// ---------------- main: 127 pair-steps + 1 single step ----------------------
__global__ void __launch_bounds__(256, 1) mps_chain(
    const float* __restrict__ x, const float* __restrict__ core0,
    const float* __restrict__ classifier, float* __restrict__ out)
{
    __shared__ char sm[SMEM_MAIN];
    uint32_t smb = smem_u32(sm);
    const int tid = threadIdx.x, lane = tid & 31, wc = tid >> 5;
    const int b0 = blockIdx.x * 16;

    float* XS   = (float*)(sm + XS_OFF);
    float* LOGS = (float*)(sm + LG_OFF);
    float* RINV = (float*)(sm + RI_OFF);
    float* LTOT = (float*)(sm + LT_OFF);

    #pragma unroll
    for (int it = 0; it < 16; ++it) {
        int idx = it * 256 + tid;
        XS[idx] = x[(size_t)(b0 + (idx >> 8)) * 256 + (idx & 255)];
    }
    if (tid < 16) LOGS[tid] = 0.f;
    __syncthreads();

    // init V0[bb][h]
    #pragma unroll
    for (int it = 0; it < 8; ++it) {
        int idx = it * 256 + tid;
        int bb = idx >> 7, h = idx & 127;
        float xv = XS[bb * 256];
        float v = (1.f - xv) * core0[h] + xv * core0[HD + h];
        *(__half*)(sm + V0_OFF + bb * (PITCHV * 2) + h * 2) = __float2half_rn(v);
    }
    // step 0's leading barrier covers visibility

    const int l15 = lane & 15, lhi = (lane >> 4) << 3;
    const int r = lane >> 2, q = lane & 3;
    const float wq = (q & 1) ? 1.f : 0.f;      // selects xb multiply
    const uint32_t fb_pair = (uint32_t)(wc * 1024) + lane;   // uint4 units within a p-block

    // X = H0(0)
    uint4 X[16], Y[16];
    {
        const uint4* bp = (const uint4*)g_pairperm + fb_pair;
        #pragma unroll
        for (int nt = 0; nt < 4; ++nt)
            #pragma unroll
            for (int kp = 0; kp < 4; ++kp)
                X[nt * 4 + kp] = bp[nt * 128 + kp * 32];
    }

    for (int p = 0; p < 127; ++p) {
        // ---- load Y = H1(p) (used ~600cyc later in block2) ----
        {
            const uint4* bp = (const uint4*)g_pairperm + ((size_t)p << 13) + fb_pair + 512;
            #pragma unroll
            for (int nt = 0; nt < 4; ++nt)
                #pragma unroll
                for (int kp = 0; kp < 4; ++kp)
                    Y[nt * 4 + kp] = bp[nt * 128 + kp * 32];
        }

        const uint32_t vr = smb + ((p & 1) ? V1_OFF : V0_OFF);
        char* vw = sm + ((p & 1) ? V0_OFF : V1_OFF);

        __syncthreads();   // V(p) visible

        uint32_t acc[8][2];
        #pragma unroll
        for (int i = 0; i < 8; ++i) { acc[i][0] = 0u; acc[i][1] = 0u; }

        // ---- block 1: nt 0..3 with X, rolling A ----
        {
            uint32_t Aa[4], Ab[4];
            ldm_x4(Aa, vr + (uint32_t)(l15 * PITCHV + lhi) * 2);
            #pragma unroll
            for (int kc = 0; kc < 8; ++kc) {
                uint32_t* Ac = (kc & 1) ? Ab : Aa;
                uint32_t* An = (kc & 1) ? Aa : Ab;
                if (kc + 1 < 8)
                    ldm_x4(An, vr + (uint32_t)(l15 * PITCHV + (kc + 1) * 16 + lhi) * 2);
                #pragma unroll
                for (int nt = 0; nt < 4; ++nt) {
                    const uint4& v = X[nt * 4 + (kc >> 1)];
                    mma16816h(acc[nt], Ac, (kc & 1) ? v.z : v.x, (kc & 1) ? v.w : v.y);
                }
            }
        }

        // ---- load X = H0(p+1) / last-site fragments (used next step) ----
        {
            const uint4* bp = (p < 126)
                ? (const uint4*)g_pairperm + ((size_t)(p + 1) << 13) + fb_pair
                : (const uint4*)g_permlast + (uint32_t)(wc * 512) + lane;
            #pragma unroll
            for (int nt = 0; nt < 4; ++nt)
                #pragma unroll
                for (int kp = 0; kp < 4; ++kp)
                    X[nt * 4 + kp] = bp[nt * 128 + kp * 32];
        }

        // ---- block 2: nt 4..7 with Y, rolling A (re-read) ----
        {
            uint32_t Aa[4], Ab[4];
            ldm_x4(Aa, vr + (uint32_t)(l15 * PITCHV + lhi) * 2);
            #pragma unroll
            for (int kc = 0; kc < 8; ++kc) {
                uint32_t* Ac = (kc & 1) ? Ab : Aa;
                uint32_t* An = (kc & 1) ? Aa : Ab;
                if (kc + 1 < 8)
                    ldm_x4(An, vr + (uint32_t)(l15 * PITCHV + (kc + 1) * 16 + lhi) * 2);
                #pragma unroll
                for (int nt = 0; nt < 4; ++nt) {
                    const uint4& v = Y[nt * 4 + (kc >> 1)];
                    mma16816h(acc[4 + nt], Ac, (kc & 1) ? v.z : v.x, (kc & 1) ? v.w : v.y);
                }
            }
        }

        // ---- epilogue: combine 4 combos; V_new = 64 * (t(q) + t(q^1)) ----
        const float xa_r = XS[r * 256 + 2 * p + 1],       xb_r = XS[r * 256 + 2 * p + 2];
        const float xa_s = XS[(r + 8) * 256 + 2 * p + 1], xb_s = XS[(r + 8) * 256 + 2 * p + 2];
        const float mb_r = (q & 1) ? xb_r : 1.f;
        const float mb_s = (q & 1) ? xb_s : 1.f;
        #pragma unroll
        for (int nt = 0; nt < 8; ++nt) {
            float2 f0 = __half22float2(*(const __half2*)&acc[nt][0]);
            float2 f1 = __half22float2(*(const __half2*)&acc[nt][1]);
            float t0 = mb_r * fmaf(xa_r, f0.y, f0.x);
            float t1 = mb_s * fmaf(xa_s, f1.y, f1.x);
            t0 += __shfl_xor_sync(0xffffffffu, t0, 1);
            t1 += __shfl_xor_sync(0xffffffffu, t1, 1);
            if (!(q & 1)) {
                int h = wc * 16 + nt * 2 + (q >> 1);
                *(__half*)(vw + r * (PITCHV * 2) + h * 2) = __float2half_rn(64.f * t0);
                *(__half*)(vw + (r + 8) * (PITCHV * 2) + h * 2) = __float2half_rn(64.f * t1);
            }
        }

        if (((p + 1) & 7) == 0 && p < 126)
            renorm(vw, LOGS, RINV);
        // visibility covered by next step's leading barrier
    }

    // ---- last single step: site 255 = cores[254], B in X ----
    {
        const uint32_t vr = smb + V1_OFF;   // p=126 wrote V1
        char* vw = sm + V0_OFF;
        __syncthreads();

        uint32_t acc[4][2];
        #pragma unroll
        for (int i = 0; i < 4; ++i) { acc[i][0] = 0u; acc[i][1] = 0u; }

        uint32_t Aa[4], Ab[4];
        ldm_x4(Aa, vr + (uint32_t)(l15 * PITCHV + lhi) * 2);
        #pragma unroll
        for (int kc = 0; kc < 8; ++kc) {
            uint32_t* Ac = (kc & 1) ? Ab : Aa;
            uint32_t* An = (kc & 1) ? Aa : Ab;
            if (kc + 1 < 8)
                ldm_x4(An, vr + (uint32_t)(l15 * PITCHV + (kc + 1) * 16 + lhi) * 2);
            #pragma unroll
            for (int nt = 0; nt < 4; ++nt) {
                const uint4& v = X[nt * 4 + (kc >> 1)];
                mma16816h(acc[nt], Ac, (kc & 1) ? v.z : v.x, (kc & 1) ? v.w : v.y);
            }
        }

        const float xa = XS[r * 256 + 255];
        const float xb = XS[(r + 8) * 256 + 255];
        #pragma unroll
        for (int nt = 0; nt < 4; ++nt) {
            int h = wc * 16 + nt * 4 + q;
            float2 f0 = __half22float2(*(const __half2*)&acc[nt][0]);
            float2 f1 = __half22float2(*(const __half2*)&acc[nt][1]);
            float v0 = 8.f * fmaf(xa, f0.y, (1.f - xa) * f0.x);
            float v1 = 8.f * fmaf(xb, f1.y, (1.f - xb) * f1.x);
            *(__half*)(vw + r * (PITCHV * 2) + h * 2) = __float2half_rn(v0);
            *(__half*)(vw + (r + 8) * (PITCHV * 2) + h * 2) = __float2half_rn(v1);
        }
    }
    __syncthreads();

    // final norm + total log (V in V0)
    {
        int bb = tid >> 4, seg = tid & 15;
        const __half* vrow = (const __half*)(sm + V0_OFF + bb * (PITCHV * 2));
        float s = 0.f;
        #pragma unroll
        for (int j = 0; j < 8; ++j) {
            float f = __half2float(vrow[seg * 8 + j]);
            s = fmaf(f, f, s);
        }
        #pragma unroll
        for (int o = 8; o > 0; o >>= 1) s += __shfl_xor_sync(0xffffffffu, s, o);
        if (seg == 0) {
            float nrm = fmaxf(sqrtf(s), 1e-30f);
            RINV[bb] = 1.f / nrm;
            LTOT[bb] = LOGS[bb] + logf(nrm) - LOG_CORR;
        }
    }
    __syncthreads();

    if (tid < 16 * OUTC) {
        int bb = tid / OUTC, o = tid % OUTC;
        const __half* vrow = (const __half*)(sm + V0_OFF + bb * (PITCHV * 2));
        float s = 0.f;
        #pragma unroll
        for (int h = 0; h < HD; ++h)
            s = fmaf(__half2float(vrow[h]), classifier[o * HD + h], s);
        out[(size_t)(b0 + bb) * OUTC + o] = s * RINV[bb] + LTOT[bb];
    }
}

extern "C" void kernel_launch(void* const* d_in, const int* in_sizes, int n_in,
                              void* d_out, int out_size)
{
    (void)in_sizes; (void)n_in; (void)out_size;
    const float* x          = (const float*)d_in[0];
    const float* core0      = (const float*)d_in[1];
    const float* cores      = (const float*)d_in[2];
    const float* classifier = (const float*)d_in[3];
    float*       out        = (float*)d_out;

    cudaFuncSetAttribute(pp_kernel, cudaFuncAttributeMaxDynamicSharedMemorySize,
                         128 * 136 * 2 * 2);

    pp_kernel<<<dim3(4, 127), 256, 128 * 136 * 2 * 2>>>(cores);
    perm_pairs<<<16256, 256>>>();
    conv_last<<<64, 256>>>(cores);
    mps_chain<<<4, 256>>>(x, core0, classifier, out);
}

// round 17
// speedup vs baseline: 1.3561x; 1.3561x over previous
#include <cuda_runtime.h>
#include <cuda_fp16.h>
#include <math.h>
#include <stdint.h>

#define BATCH  64
#define HD     128
#define OUTC   10

#define PITCHV 136      // V row pitch, fp16 elems
#define V0_OFF 0
#define V1_OFF (16 * PITCHV * 2)            // 4352
#define XS_OFF (2 * 16 * PITCHV * 2)        // 8704
#define LG_OFF (XS_OFF + 16 * 256 * 4)      // 25088
#define RI_OFF (LG_OFF + 64)
#define LT_OFF (RI_OFF + 64)
#define SMEM_MAIN (LT_OFF + 64)

// exact correction for per-step x4 scale: 255 * ln(4)
#define LOG_CORR 353.50507f

// Chain matrices in B-fragment order, d-plane layout (fp16 pairs in u32, 16.7 MB):
// columns: n in [0,128) = (d=0, h=n); n in [128,256) = (d=1, h=n-128)
// uint4 index: m*4096 + c8*128 + kp*32 + lane,  c8 = n>>3  (0..31)
//   within uint4, u32 j: kc = 2*kp + (j>>1); reg = j&1
//   packed pair = M[k0][n], M[k0+1][n]; k0 = kc*16 + 2*(lane&3) + reg*8
//   n = c8*8 + (lane>>2);  M[k][n] = cores[m][k][n>>7][n&127]
__device__ uint32_t g_perm[(size_t)255 * 16384];

// ---------------- helpers ----------------
__device__ __forceinline__ uint32_t smem_u32(const void* p) {
    uint32_t a;
    asm("{ .reg .u64 t; cvta.to.shared.u64 t, %1; cvt.u32.u64 %0, t; }" : "=r"(a) : "l"(p));
    return a;
}
__device__ __forceinline__ void ldm_x4(uint32_t* r, uint32_t addr) {
    asm volatile("ldmatrix.sync.aligned.m8n8.x4.shared.b16 {%0,%1,%2,%3}, [%4];"
                 : "=r"(r[0]), "=r"(r[1]), "=r"(r[2]), "=r"(r[3]) : "r"(addr));
}
// f16-accumulate HMMA
__device__ __forceinline__ void mma16816h(uint32_t* c, const uint32_t* a,
                                          uint32_t b0, uint32_t b1) {
    asm volatile(
        "mma.sync.aligned.m16n8k16.row.col.f16.f16.f16.f16 "
        "{%0,%1}, {%2,%3,%4,%5}, {%6,%7}, {%0,%1};"
        : "+r"(c[0]), "+r"(c[1])
        : "r"(a[0]), "r"(a[1]), "r"(a[2]), "r"(a[3]), "r"(b0), "r"(b1));
}
__device__ __forceinline__ uint32_t packh2(float a, float b) {
    __half2 t = __floats2half2_rn(a, b);
    return *reinterpret_cast<uint32_t*>(&t);
}

// ---------------- pre-pass: coalesced SMEM-staged fragment permute ----------
// d-plane layout: within a k-row of cores (256 floats, [d][h] d-major),
// column n of M is simply source index n. (d = n>>7, h = n&127)
__global__ void __launch_bounds__(256) conv_perm(const float* __restrict__ cores)
{
    __shared__ float ts[32][257];
    const int m = blockIdx.x, tid = threadIdx.x;
    const float* src = cores + (size_t)m * 32768;
    uint32_t* dst = g_perm + (size_t)m * 16384;

    for (int kp = 0; kp < 4; ++kp) {
        #pragma unroll
        for (int it = 0; it < 8; ++it) {
            int idx = it * 256 + tid;
            int k = idx >> 6, cg = (idx & 63) * 4;
            float4 v = *(const float4*)(src + (size_t)(kp * 32 + k) * 256 + cg);
            ts[k][cg + 0] = v.x; ts[k][cg + 1] = v.y;
            ts[k][cg + 2] = v.z; ts[k][cg + 3] = v.w;
        }
        __syncthreads();
        #pragma unroll
        for (int it = 0; it < 16; ++it) {
            int lin = it * 256 + tid;
            int j    = lin & 3;
            int lane = (lin >> 2) & 31;
            int c8   = lin >> 7;
            int k0l = 16 * (j >> 1) + 2 * (lane & 3) + ((j & 1) << 3);
            int n = c8 * 8 + (lane >> 2);
            float lo = ts[k0l][n];
            float hi = ts[k0l + 1][n];
            dst[(size_t)c8 * 512 + kp * 128 + (lin & 127)] = packh2(lo, hi);
        }
        __syncthreads();
    }
}

// ---------------- one chain step ----------------
// Warp wc covers h in [wc*16, wc*16+16): acc[0],acc[1] = U (plane d=0,
// c8 = 2wc, 2wc+1); acc[2],acc[3] = W (plane d=1, c8 = 16+2wc, 17+2wc).
// Thread's col pair = adjacent h (h0 = base+2q, h0+1) -> one ST.32 per row.
__device__ __forceinline__ void chain_step(
    int m, bool prefetch, uint4* __restrict__ Bcur, uint4* __restrict__ Bnext,
    char* sm, uint32_t smb, uint32_t fragbase,
    int lane, int wc, int l15, int lhi, int r, int q)
{
    float* XS   = (float*)(sm + XS_OFF);
    float* LOGS = (float*)(sm + LG_OFF);
    float* RINV = (float*)(sm + RI_OFF);

    // prefetch B(m+1): 16 coalesced LDG.128
    if (prefetch) {
        const uint4* bp = (const uint4*)g_perm + ((size_t)(m + 1) << 12) + fragbase;
        #pragma unroll
        for (int nt = 0; nt < 4; ++nt) {
            uint32_t c8 = (nt < 2) ? (uint32_t)(2 * wc + nt) : (uint32_t)(16 + 2 * wc + (nt - 2));
            #pragma unroll
            for (int kp = 0; kp < 4; ++kp)
                Bnext[nt * 4 + kp] = bp[c8 * 128 + kp * 32];
        }
    }

    const uint32_t vr = smb + ((m & 1) ? V1_OFF : V0_OFF);
    char* vw = sm + ((m & 1) ? V0_OFF : V1_OFF);

    __syncthreads();   // V(m) writes visible

    uint32_t acc[4][2];
    #pragma unroll
    for (int i = 0; i < 4; ++i) { acc[i][0] = 0u; acc[i][1] = 0u; }

    // interleaved A-ldmatrix / MMA
    uint32_t A[8][4];
    ldm_x4(A[0], vr + (uint32_t)(l15 * PITCHV + 0 * 16 + lhi) * 2);
    ldm_x4(A[1], vr + (uint32_t)(l15 * PITCHV + 1 * 16 + lhi) * 2);
    #pragma unroll
    for (int kc = 0; kc < 8; ++kc) {
        if (kc + 2 < 8)
            ldm_x4(A[kc + 2], vr + (uint32_t)(l15 * PITCHV + (kc + 2) * 16 + lhi) * 2);
        #pragma unroll
        for (int nt = 0; nt < 4; ++nt) {
            const uint4& v = Bcur[nt * 4 + (kc >> 1)];
            uint32_t b0 = (kc & 1) ? v.z : v.x;
            uint32_t b1 = (kc & 1) ? v.w : v.y;
            mma16816h(acc[nt], A[kc], b0, b1);
        }
    }

    // epilogue: V_new(h pair) = 4*((1-x)*U + x*W), one ST.32 per (j,row)
    const float xa = XS[r * 256 + m + 1];
    const float xb = XS[(r + 8) * 256 + m + 1];
    #pragma unroll
    for (int j = 0; j < 2; ++j) {
        int h0 = wc * 16 + j * 8 + 2 * q;
        float2 u0 = __half22float2(*(const __half2*)&acc[j][0]);      // U rows r
        float2 u1 = __half22float2(*(const __half2*)&acc[j][1]);      // U rows r+8
        float2 w0 = __half22float2(*(const __half2*)&acc[2 + j][0]);  // W rows r
        float2 w1 = __half22float2(*(const __half2*)&acc[2 + j][1]);  // W rows r+8
        float a0 = 4.f * fmaf(xa, w0.x, (1.f - xa) * u0.x);
        float a1 = 4.f * fmaf(xa, w0.y, (1.f - xa) * u0.y);
        float b0 = 4.f * fmaf(xb, w1.x, (1.f - xb) * u1.x);
        float b1 = 4.f * fmaf(xb, w1.y, (1.f - xb) * u1.y);
        *(uint32_t*)(vw + r * (PITCHV * 2) + h0 * 2) = packh2(a0, a1);
        *(uint32_t*)(vw + (r + 8) * (PITCHV * 2) + h0 * 2) = packh2(b0, b1);
    }

    // renormalize every 16 steps
    if (((m + 1) & 15) == 0 && m < 254) {
        const int tid = threadIdx.x;
        __syncthreads();
        int bb = tid >> 4, seg = tid & 15;
        __half* vrow = (__half*)(vw + bb * (PITCHV * 2));
        float s = 0.f;
        #pragma unroll
        for (int j = 0; j < 8; ++j) {
            float f = __half2float(vrow[seg * 8 + j]);
            s = fmaf(f, f, s);
        }
        #pragma unroll
        for (int o = 8; o > 0; o >>= 1) s += __shfl_xor_sync(0xffffffffu, s, o);
        if (seg == 0) {
            float nrm = fmaxf(sqrtf(s), 1e-30f);
            LOGS[bb] += logf(nrm);
            RINV[bb] = 1.f / nrm;
        }
        __syncthreads();
        float ri = RINV[bb];
        #pragma unroll
        for (int j = 0; j < 8; ++j)
            vrow[seg * 8 + j] = __float2half_rn(__half2float(vrow[seg * 8 + j]) * ri);
        // visibility covered by next step's leading barrier
    }
}

// ---------------- main: batched vector chain ----------------
__global__ void __launch_bounds__(256, 1) mps_chain(
    const float* __restrict__ x, const float* __restrict__ core0,
    const float* __restrict__ classifier, float* __restrict__ out)
{
    __shared__ char sm[SMEM_MAIN];
    uint32_t smb = smem_u32(sm);
    const int tid = threadIdx.x, lane = tid & 31, wc = tid >> 5;
    const int b0 = blockIdx.x * 16;

    float* XS   = (float*)(sm + XS_OFF);
    float* LOGS = (float*)(sm + LG_OFF);
    float* RINV = (float*)(sm + RI_OFF);
    float* LTOT = (float*)(sm + LT_OFF);

    #pragma unroll
    for (int it = 0; it < 16; ++it) {
        int idx = it * 256 + tid;
        XS[idx] = x[(size_t)(b0 + (idx >> 8)) * 256 + (idx & 255)];
    }
    if (tid < 16) LOGS[tid] = 0.f;
    __syncthreads();

    // init V0[bb][h]
    #pragma unroll
    for (int it = 0; it < 8; ++it) {
        int idx = it * 256 + tid;
        int bb = idx >> 7, h = idx & 127;
        float xv = XS[bb * 256];
        float v = (1.f - xv) * core0[h] + xv * core0[HD + h];
        *(__half*)(sm + V0_OFF + bb * (PITCHV * 2) + h * 2) = __float2half_rn(v);
    }
    // step 0's leading barrier covers visibility

    const int l15 = lane & 15, lhi = (lane >> 4) << 3;
    const int r = lane >> 2, q = lane & 3;
    const uint32_t fragbase = lane;     // uint4 units; c8 offsets added per nt

    // preload B(0)
    uint4 B0[16], B1[16];
    {
        const uint4* bp = (const uint4*)g_perm + fragbase;
        #pragma unroll
        for (int nt = 0; nt < 4; ++nt) {
            uint32_t c8 = (nt < 2) ? (uint32_t)(2 * wc + nt) : (uint32_t)(16 + 2 * wc + (nt - 2));
            #pragma unroll
            for (int kp = 0; kp < 4; ++kp)
                B0[nt * 4 + kp] = bp[c8 * 128 + kp * 32];
        }
    }

    for (int mm = 0; mm < 127; ++mm) {
        chain_step(2 * mm,     true, B0, B1, sm, smb, fragbase, lane, wc, l15, lhi, r, q);
        chain_step(2 * mm + 1, true, B1, B0, sm, smb, fragbase, lane, wc, l15, lhi, r, q);
    }
    chain_step(254, false, B0, B1, sm, smb, fragbase, lane, wc, l15, lhi, r, q);
    __syncthreads();

    // final norm + total log (V in V1); subtract exact x4-per-step correction
    {
        int bb = tid >> 4, seg = tid & 15;
        const __half* vrow = (const __half*)(sm + V1_OFF + bb * (PITCHV * 2));
        float s = 0.f;
        #pragma unroll
        for (int j = 0; j < 8; ++j) {
            float f = __half2float(vrow[seg * 8 + j]);
            s = fmaf(f, f, s);
        }
        #pragma unroll
        for (int o = 8; o > 0; o >>= 1) s += __shfl_xor_sync(0xffffffffu, s, o);
        if (seg == 0) {
            float nrm = fmaxf(sqrtf(s), 1e-30f);
            RINV[bb] = 1.f / nrm;
            LTOT[bb] = LOGS[bb] + logf(nrm) - LOG_CORR;
        }
    }
    __syncthreads();

    if (tid < 16 * OUTC) {
        int bb = tid / OUTC, o = tid % OUTC;
        const __half* vrow = (const __half*)(sm + V1_OFF + bb * (PITCHV * 2));
        float s = 0.f;
        #pragma unroll
        for (int h = 0; h < HD; ++h)
            s = fmaf(__half2float(vrow[h]), classifier[o * HD + h], s);
        out[(size_t)(b0 + bb) * OUTC + o] = s * RINV[bb] + LTOT[bb];
    }
}

extern "C" void kernel_launch(void* const* d_in, const int* in_sizes, int n_in,
                              void* d_out, int out_size)
{
    (void)in_sizes; (void)n_in; (void)out_size;
    const float* x          = (const float*)d_in[0];
    const float* core0      = (const float*)d_in[1];
    const float* cores      = (const float*)d_in[2];
    const float* classifier = (const float*)d_in[3];
    float*       out        = (float*)d_out;

    conv_perm<<<255, 256>>>(cores);
    mps_chain<<<4, 256>>>(x, core0, classifier, out);
}